// round 3
// baseline (speedup 1.0000x reference)
#include <cuda_runtime.h>

#define N_NODES 100000
#define N_EDGES 3200000
#define IN_DIM  256
#define HID     16
#define OUT_DIM 10

// Scratch (float4 arrays => 16B alignment guaranteed for red.global.add.v4.f32)
__device__ float4 g_m1[N_NODES * 4];    // x@W1              [N,16]
__device__ float4 g_agg1[N_NODES * 4];  // scatter target 1  [N,16]
__device__ float4 g_m2[N_NODES * 3];    // h@W2 padded       [N,12] (cols 10,11 = 0)
__device__ float4 g_agg2[N_NODES * 3];  // scatter target 2  [N,12] (init: b2 in 0..9)

// ---------------------------------------------------------------- init
__global__ void k_init(const float* __restrict__ b2) {
    int i = blockIdx.x * blockDim.x + threadIdx.x;
    float4 z = make_float4(0.f, 0.f, 0.f, 0.f);
    if (i < N_NODES * 4) g_agg1[i] = z;
    if (i < N_NODES * 3) {
        int q = i % 3;
        float4 v;
        if (q == 0)      v = make_float4(b2[0], b2[1], b2[2], b2[3]);
        else if (q == 1) v = make_float4(b2[4], b2[5], b2[6], b2[7]);
        else             v = make_float4(b2[8], b2[9], 0.f, 0.f);
        g_agg2[i] = v;
    }
}

// ---------------------------------------------------------------- GEMM1: m1 = x @ W1
// 256 threads = 8 warps, 2 rows per warp => 16 rows/block, 6250 blocks (exact).
__global__ void __launch_bounds__(256) k_gemm1(const float* __restrict__ x,
                                               const float* __restrict__ W1) {
    __shared__ float Wt[HID * IN_DIM];  // transposed: Wt[f*256 + k] = W1[k*16 + f]
    for (int i = threadIdx.x; i < HID * IN_DIM; i += blockDim.x) {
        int f = i >> 8, k = i & 255;
        Wt[i] = W1[k * HID + f];
    }
    __syncthreads();
    const float4* Wt4 = (const float4*)Wt;

    int lane = threadIdx.x & 31;
    int warp = threadIdx.x >> 5;
    int row0 = blockIdx.x * 16 + warp * 2;
    int row1 = row0 + 1;

    const float4* x4 = (const float4*)x;
    float4 a0 = x4[row0 * 64 + lane];
    float4 b0 = x4[row0 * 64 + 32 + lane];
    float4 a1 = x4[row1 * 64 + lane];
    float4 b1 = x4[row1 * 64 + 32 + lane];

    float acc0[HID], acc1[HID];
#pragma unroll
    for (int f = 0; f < HID; f++) {
        float4 wa = Wt4[f * 64 + lane];       // conflict-free: consecutive float4
        float4 wb = Wt4[f * 64 + 32 + lane];
        acc0[f] = a0.x * wa.x + a0.y * wa.y + a0.z * wa.z + a0.w * wa.w
                + b0.x * wb.x + b0.y * wb.y + b0.z * wb.z + b0.w * wb.w;
        acc1[f] = a1.x * wa.x + a1.y * wa.y + a1.z * wa.z + a1.w * wa.w
                + b1.x * wb.x + b1.y * wb.y + b1.z * wb.z + b1.w * wb.w;
    }
#pragma unroll
    for (int s = 16; s >= 1; s >>= 1) {
#pragma unroll
        for (int f = 0; f < HID; f++) {
            acc0[f] += __shfl_xor_sync(0xffffffffu, acc0[f], s);
            acc1[f] += __shfl_xor_sync(0xffffffffu, acc1[f], s);
        }
    }
    if (lane == 0)      g_m1[row0 * 4 + 0] = make_float4(acc0[0],  acc0[1],  acc0[2],  acc0[3]);
    else if (lane == 1) g_m1[row0 * 4 + 1] = make_float4(acc0[4],  acc0[5],  acc0[6],  acc0[7]);
    else if (lane == 2) g_m1[row0 * 4 + 2] = make_float4(acc0[8],  acc0[9],  acc0[10], acc0[11]);
    else if (lane == 3) g_m1[row0 * 4 + 3] = make_float4(acc0[12], acc0[13], acc0[14], acc0[15]);
    else if (lane == 4) g_m1[row1 * 4 + 0] = make_float4(acc1[0],  acc1[1],  acc1[2],  acc1[3]);
    else if (lane == 5) g_m1[row1 * 4 + 1] = make_float4(acc1[4],  acc1[5],  acc1[6],  acc1[7]);
    else if (lane == 6) g_m1[row1 * 4 + 2] = make_float4(acc1[8],  acc1[9],  acc1[10], acc1[11]);
    else if (lane == 7) g_m1[row1 * 4 + 3] = make_float4(acc1[12], acc1[13], acc1[14], acc1[15]);
}

// ---------------------------------------------------------------- scatter 1: agg1[dst] += m1[src]
// edge_index is int32 at runtime (JAX x64 disabled downcasts the requested int64).
// thread = (edge, quarter); vector atomic red.global.add.v4.f32 (16 floats -> 4 REDs)
__global__ void k_scatter1(const int* __restrict__ ei) {
    int t = blockIdx.x * blockDim.x + threadIdx.x;
    if (t >= N_EDGES * 4) return;
    int e = t >> 2, q = t & 3;
    int src = ei[e];
    int dst = ei[N_EDGES + e];
    if ((unsigned)src >= N_NODES || (unsigned)dst >= N_NODES) return;  // defensive
    float4 v = g_m1[src * 4 + q];
    float4* p = &g_agg1[dst * 4 + q];
    asm volatile("red.global.add.v4.f32 [%0], {%1,%2,%3,%4};"
                 :: "l"(p), "f"(v.x), "f"(v.y), "f"(v.z), "f"(v.w) : "memory");
}

// ---------------------------------------------------------------- layer 2: m2 = relu(agg1+b1) @ W2 (padded to 12)
__global__ void __launch_bounds__(128) k_layer2(const float* __restrict__ b1,
                                                const float* __restrict__ W2) {
    __shared__ float hs[128 * 17];   // padded stride 17 => conflict-free row reads
    __shared__ float W2s[HID * OUT_DIM];
    __shared__ float b1s[HID];
    int tid = threadIdx.x;
    for (int i = tid; i < HID * OUT_DIM; i += 128) W2s[i] = W2[i];  // 160 elems, strided
    if (tid < HID) b1s[tid] = b1[tid];

    int base = blockIdx.x * 128;
    const float* agg1 = (const float*)g_agg1;
    for (int i = tid; i < 128 * HID; i += 128) {
        int gi = base * HID + i;
        int r = i >> 4, f = i & 15;
        hs[r * 17 + f] = (gi < N_NODES * HID) ? agg1[gi] : 0.f;
    }
    __syncthreads();

    int node = base + tid;
    if (node >= N_NODES) return;

    float h[HID];
#pragma unroll
    for (int f = 0; f < HID; f++) {
        float v = hs[tid * 17 + f] + b1s[f];
        h[f] = v > 0.f ? v : 0.f;
    }
    float acc[OUT_DIM];
#pragma unroll
    for (int o = 0; o < OUT_DIM; o++) acc[o] = 0.f;
#pragma unroll
    for (int f = 0; f < HID; f++)
#pragma unroll
        for (int o = 0; o < OUT_DIM; o++)
            acc[o] += h[f] * W2s[f * OUT_DIM + o];  // broadcast reads

    g_m2[node * 3 + 0] = make_float4(acc[0], acc[1], acc[2], acc[3]);
    g_m2[node * 3 + 1] = make_float4(acc[4], acc[5], acc[6], acc[7]);
    g_m2[node * 3 + 2] = make_float4(acc[8], acc[9], 0.f, 0.f);  // zero padding cols
}

// ---------------------------------------------------------------- scatter 2: agg2[dst] += m2[src] (12 padded floats -> 3 REDs)
__global__ void k_scatter2(const int* __restrict__ ei) {
    int t = blockIdx.x * blockDim.x + threadIdx.x;
    if (t >= N_EDGES * 3) return;
    int e = t / 3, q = t - e * 3;
    int src = ei[e];
    int dst = ei[N_EDGES + e];
    if ((unsigned)src >= N_NODES || (unsigned)dst >= N_NODES) return;  // defensive
    float4 v = g_m2[src * 3 + q];
    float4* p = &g_agg2[dst * 3 + q];
    asm volatile("red.global.add.v4.f32 [%0], {%1,%2,%3,%4};"
                 :: "l"(p), "f"(v.x), "f"(v.y), "f"(v.z), "f"(v.w) : "memory");
}

// ---------------------------------------------------------------- output: strip padding
__global__ void k_out(float* __restrict__ out) {
    int i = blockIdx.x * blockDim.x + threadIdx.x;
    if (i >= N_NODES * OUT_DIM) return;
    int n = i / OUT_DIM, f = i - n * OUT_DIM;
    out[i] = ((const float*)g_agg2)[n * 12 + f];
}

// ---------------------------------------------------------------- launch
extern "C" void kernel_launch(void* const* d_in, const int* in_sizes, int n_in,
                              void* d_out, int out_size) {
    const float* x  = (const float*)d_in[0];
    const int*   ei = (const int*)d_in[1];   // int32: JAX default x64-disabled
    const float* W1 = (const float*)d_in[2];
    const float* b1 = (const float*)d_in[3];
    const float* W2 = (const float*)d_in[4];
    const float* b2 = (const float*)d_in[5];
    float* out = (float*)d_out;

    k_init    <<<(N_NODES * 4 + 255) / 256, 256>>>(b2);
    k_gemm1   <<<N_NODES / 16, 256>>>(x, W1);
    k_scatter1<<<(N_EDGES * 4 + 255) / 256, 256>>>(ei);
    k_layer2  <<<(N_NODES + 127) / 128, 128>>>(b1, W2);
    k_scatter2<<<(N_EDGES * 3 + 191) / 192, 192>>>(ei);
    k_out     <<<(N_NODES * OUT_DIM + 255) / 256, 256>>>(out);
}